// round 3
// baseline (speedup 1.0000x reference)
#include <cuda_runtime.h>
#include <math.h>
#include <stdint.h>

#define MAXN    2048
#define WWORDS  32          // 2048 / 64 bits
#define EPSF    1e-8f
#define NMS_THR 0.7f

// ---- device scratch (no allocations allowed) ----
__device__ float g_cx[MAXN * 4];
__device__ float g_cy[MAXN * 4];
__device__ float g_bx[MAXN];
__device__ float g_by[MAXN];
__device__ float g_area[MAXN];
__device__ float g_rad[MAXN];
__device__ unsigned long long g_mask[MAXN * WWORDS];

// ---------------------------------------------------------------------------
// Kernel 1: zero the suppression mask; compute corners / areas / bounding radii
// ---------------------------------------------------------------------------
__global__ void prep_kernel(const float* __restrict__ boxes, int N)
{
    int tid = blockIdx.x * blockDim.x + threadIdx.x;
    if (tid < MAXN * WWORDS) g_mask[tid] = 0ULL;
    if (tid < N) {
        float xc = boxes[tid * 5 + 0];
        float yc = boxes[tid * 5 + 1];
        float w  = boxes[tid * 5 + 2];
        float h  = boxes[tid * 5 + 3];
        float t  = boxes[tid * 5 + 4];
        float th = t * (float)(M_PI / 180.0);
        float c = cosf(th), s = sinf(th);
        const float lx[4] = { 0.5f, -0.5f, -0.5f,  0.5f };
        const float ly[4] = { 0.5f,  0.5f, -0.5f, -0.5f };
#pragma unroll
        for (int k = 0; k < 4; ++k) {
            g_cx[tid * 4 + k] = xc + lx[k] * w * c - ly[k] * h * s;
            g_cy[tid * 4 + k] = yc + lx[k] * w * s + ly[k] * h * c;
        }
        g_bx[tid] = xc;
        g_by[tid] = yc;
        g_area[tid] = w * h;
        g_rad[tid]  = 0.5f * sqrtf(w * w + h * h);
    }
}

// ---------------------------------------------------------------------------
// Kernel 2: pairwise rotated IoU -> suppression bitmask (j > i only)
// Replicates the reference's 24-point construction + stable angle sort +
// shoelace, with invalid points compacted out (exactly equivalent fp math:
// invalid points contribute exact-zero terms in the reference).
// ---------------------------------------------------------------------------
__global__ void iou_kernel(int N)
{
    long long tid = (long long)blockIdx.x * blockDim.x + threadIdx.x;
    if (tid >= (long long)N * N) return;
    int i = (int)(tid / N);
    int j = (int)(tid - (long long)i * N);
    if (j <= i) return;

    // bounding-circle quick reject (conservative: no contact -> inter == 0)
    {
        float dx = g_bx[i] - g_bx[j];
        float dy = g_by[i] - g_by[j];
        float rr = g_rad[i] + g_rad[j];
        if (dx * dx + dy * dy > rr * rr) return;
    }

    float p1x[4], p1y[4], q1x[4], q1y[4];
#pragma unroll
    for (int k = 0; k < 4; ++k) {
        p1x[k] = g_cx[i * 4 + k];  p1y[k] = g_cy[i * 4 + k];
        q1x[k] = g_cx[j * 4 + k];  q1y[k] = g_cy[j * 4 + k];
    }
    float d1x[4], d1y[4], d2x[4], d2y[4];
#pragma unroll
    for (int k = 0; k < 4; ++k) {
        int kn = (k + 1) & 3;
        d1x[k] = p1x[kn] - p1x[k];  d1y[k] = p1y[kn] - p1y[k];
        d2x[k] = q1x[kn] - q1x[k];  d2y[k] = q1y[kn] - q1y[k];
    }

    // candidate points, compacted in reference concat order
    float vx[24], vy[24], va[24];
    int nv = 0;

    // 16 edge-edge intersections, a (edges of box i) outer, b inner
#pragma unroll
    for (int a = 0; a < 4; ++a) {
#pragma unroll
        for (int b = 0; b < 4; ++b) {
            float denom = d1x[a] * d2y[b] - d1y[a] * d2x[b];
            if (fabsf(denom) > EPSF) {
                float rpx = q1x[b] - p1x[a];
                float rpy = q1y[b] - p1y[a];
                float t = (rpx * d2y[b] - rpy * d2x[b]) / denom;
                float u = (rpx * d1y[a] - rpy * d1x[a]) / denom;
                if (t >= 0.0f && t <= 1.0f && u >= 0.0f && u <= 1.0f) {
                    vx[nv] = p1x[a] + t * d1x[a];
                    vy[nv] = p1y[a] + t * d1y[a];
                    ++nv;
                }
            }
        }
    }

    // corners of box i inside box j
#pragma unroll
    for (int a = 0; a < 4; ++a) {
        bool ge = true, le = true;
#pragma unroll
        for (int b = 0; b < 4; ++b) {
            float cvx = p1x[a] - q1x[b];
            float cvy = p1y[a] - q1y[b];
            float cr = d2x[b] * cvy - d2y[b] * cvx;
            ge = ge && (cr >= -EPSF);
            le = le && (cr <=  EPSF);
        }
        if (ge || le) { vx[nv] = p1x[a]; vy[nv] = p1y[a]; ++nv; }
    }
    // corners of box j inside box i
#pragma unroll
    for (int b = 0; b < 4; ++b) {
        bool ge = true, le = true;
#pragma unroll
        for (int a = 0; a < 4; ++a) {
            float cvx = q1x[b] - p1x[a];
            float cvy = q1y[b] - p1y[a];
            float cr = d1x[a] * cvy - d1y[a] * cvx;
            ge = ge && (cr >= -EPSF);
            le = le && (cr <=  EPSF);
        }
        if (ge || le) { vx[nv] = q1x[b]; vy[nv] = q1y[b]; ++nv; }
    }

    float inter = 0.0f;
    if (nv >= 3) {
        float sx = 0.0f, sy = 0.0f;
        for (int k = 0; k < nv; ++k) { sx += vx[k]; sy += vy[k]; }
        float cx = sx / (float)nv;
        float cy = sy / (float)nv;
        for (int k = 0; k < nv; ++k)
            va[k] = atan2f(vy[k] - cy, vx[k] - cx);

        // stable insertion sort by angle (strict > keeps stability)
        for (int k = 1; k < nv; ++k) {
            float a = va[k], x = vx[k], y = vy[k];
            int m = k - 1;
            while (m >= 0 && va[m] > a) {
                va[m + 1] = va[m]; vx[m + 1] = vx[m]; vy[m + 1] = vy[m];
                --m;
            }
            va[m + 1] = a; vx[m + 1] = x; vy[m + 1] = y;
        }

        float s = 0.0f;
        for (int k = 0; k < nv; ++k) {
            int kn = (k + 1 == nv) ? 0 : k + 1;
            s += (vx[k] - cx) * (vy[kn] - cy) - (vy[k] - cy) * (vx[kn] - cx);
        }
        inter = 0.5f * fabsf(s);
    }

    float uni = g_area[i] + g_area[j] - inter;
    float iou = inter / fmaxf(uni, EPSF);
    if (iou > NMS_THR) {
        atomicOr(&g_mask[i * WWORDS + (j >> 6)], 1ULL << (j & 63));
    }
}

// ---------------------------------------------------------------------------
// Kernel 3: sequential greedy suppression (1 warp, bitmask in registers)
// + index compaction into the output (FLOAT32 indices, padded with -1.0f)
// ---------------------------------------------------------------------------
__global__ void nms_kernel(float* __restrict__ out, int N, int out_size)
{
    int lane = threadIdx.x;  // 32 lanes, lane l owns remove-word l
    unsigned long long rem = 0ULL;

    for (int i = 0; i < N; ++i) {
        int w = i >> 6, b = i & 63;
        unsigned long long row = g_mask[i * WWORDS + lane];   // independent load
        unsigned long long rw  = __shfl_sync(0xffffffffu, rem, w);
        bool sup = (rw >> b) & 1ULL;
        if (!sup) rem |= row;
    }

    __shared__ unsigned long long sh[WWORDS];
    sh[lane] = rem;
    __syncwarp();
    if (lane == 0) {
        int cnt = 0;
        for (int i = 0; i < N && cnt < out_size; ++i) {
            if (!((sh[i >> 6] >> (i & 63)) & 1ULL)) out[cnt++] = (float)i;
        }
        for (; cnt < out_size; ++cnt) out[cnt] = -1.0f;
    }
}

// ---------------------------------------------------------------------------
extern "C" void kernel_launch(void* const* d_in, const int* in_sizes, int n_in,
                              void* d_out, int out_size)
{
    const float* boxes = (const float*)d_in[0];
    int N = in_sizes[0] / 5;
    if (N > MAXN) N = MAXN;
    float* out = (float*)d_out;

    {
        int total = MAXN * WWORDS;           // covers mask zeroing and N boxes
        int threads = 256;
        int blocks = (total + threads - 1) / threads;
        prep_kernel<<<blocks, threads>>>(boxes, N);
    }
    {
        long long total = (long long)N * N;
        int threads = 256;
        int blocks = (int)((total + threads - 1) / threads);
        iou_kernel<<<blocks, threads>>>(N);
    }
    nms_kernel<<<1, 32>>>(out, N, out_size);
}

// round 4
// speedup vs baseline: 2.2739x; 2.2739x over previous
#include <cuda_runtime.h>
#include <math.h>
#include <stdint.h>

#define MAXN     2048
#define WWORDS   32          // 2048 / 64 bits
#define EPSF     1e-8f
#define NMS_THR  0.7f
#define MAXPAIRS (MAXN * MAXN / 2)

// ---- device scratch (no allocations allowed) ----
__device__ float g_cx[MAXN * 4];
__device__ float g_cy[MAXN * 4];
__device__ float g_bx[MAXN];
__device__ float g_by[MAXN];
__device__ float g_area[MAXN];
__device__ float g_rad[MAXN];
__device__ unsigned long long g_mask[MAXN * WWORDS];
__device__ unsigned int g_pairs[MAXPAIRS];
__device__ int g_npairs;

// ---------------------------------------------------------------------------
// Kernel 1: zero mask + pair count; compute corners / areas / bounding radii
// ---------------------------------------------------------------------------
__global__ void prep_kernel(const float* __restrict__ boxes, int N)
{
    int tid = blockIdx.x * blockDim.x + threadIdx.x;
    if (tid == 0) g_npairs = 0;
    if (tid < MAXN * WWORDS) g_mask[tid] = 0ULL;
    if (tid < N) {
        float xc = boxes[tid * 5 + 0];
        float yc = boxes[tid * 5 + 1];
        float w  = boxes[tid * 5 + 2];
        float h  = boxes[tid * 5 + 3];
        float t  = boxes[tid * 5 + 4];
        float th = t * (float)(M_PI / 180.0);
        float c = cosf(th), s = sinf(th);
        const float lx[4] = { 0.5f, -0.5f, -0.5f,  0.5f };
        const float ly[4] = { 0.5f,  0.5f, -0.5f, -0.5f };
#pragma unroll
        for (int k = 0; k < 4; ++k) {
            g_cx[tid * 4 + k] = xc + lx[k] * w * c - ly[k] * h * s;
            g_cy[tid * 4 + k] = yc + lx[k] * w * s + ly[k] * h * c;
        }
        g_bx[tid] = xc;
        g_by[tid] = yc;
        g_area[tid] = w * h;
        g_rad[tid]  = 0.5f * sqrtf(w * w + h * h);
    }
}

// ---------------------------------------------------------------------------
// Kernel 2a: bounding-circle pre-filter -> dense worklist of candidate pairs
// (warp-aggregated atomic append; packed (i<<11)|j, j > i)
// ---------------------------------------------------------------------------
__global__ void pairgen_kernel(int N)
{
    long long tid = (long long)blockIdx.x * blockDim.x + threadIdx.x;
    int lane = threadIdx.x & 31;

    bool surv = false;
    int i = 0, j = 0;
    if (tid < (long long)N * N) {
        i = (int)(tid / N);
        j = (int)(tid - (long long)i * N);
        if (j > i) {
            float dx = g_bx[i] - g_bx[j];
            float dy = g_by[i] - g_by[j];
            float rr = g_rad[i] + g_rad[j];
            surv = (dx * dx + dy * dy <= rr * rr);
        }
    }

    unsigned m = __ballot_sync(0xffffffffu, surv);
    if (m) {
        int cnt = __popc(m);
        int leader = __ffs(m) - 1;
        int base = 0;
        if (lane == leader) base = atomicAdd(&g_npairs, cnt);
        base = __shfl_sync(0xffffffffu, base, leader);
        if (surv) {
            int pos = base + __popc(m & ((1u << lane) - 1u));
            g_pairs[pos] = ((unsigned)i << 11) | (unsigned)j;
        }
    }
}

// ---------------------------------------------------------------------------
// Kernel 2b: dense polygon-clip IoU over the worklist -> suppression bitmask.
// Replicates the reference's 24-point construction + stable angle sort +
// shoelace, with invalid points compacted out (exactly equivalent fp math).
// ---------------------------------------------------------------------------
__global__ void clip_kernel(int N)
{
    int np = g_npairs;
    int stride = gridDim.x * blockDim.x;
    for (int idx = blockIdx.x * blockDim.x + threadIdx.x; idx < np; idx += stride) {
        unsigned pr = g_pairs[idx];
        int i = (int)(pr >> 11);
        int j = (int)(pr & 0x7FFu);

        float p1x[4], p1y[4], q1x[4], q1y[4];
#pragma unroll
        for (int k = 0; k < 4; ++k) {
            p1x[k] = g_cx[i * 4 + k];  p1y[k] = g_cy[i * 4 + k];
            q1x[k] = g_cx[j * 4 + k];  q1y[k] = g_cy[j * 4 + k];
        }
        float d1x[4], d1y[4], d2x[4], d2y[4];
#pragma unroll
        for (int k = 0; k < 4; ++k) {
            int kn = (k + 1) & 3;
            d1x[k] = p1x[kn] - p1x[k];  d1y[k] = p1y[kn] - p1y[k];
            d2x[k] = q1x[kn] - q1x[k];  d2y[k] = q1y[kn] - q1y[k];
        }

        float vx[24], vy[24], va[24];
        int nv = 0;

        // 16 edge-edge intersections, a (edges of box i) outer, b inner
#pragma unroll
        for (int a = 0; a < 4; ++a) {
#pragma unroll
            for (int b = 0; b < 4; ++b) {
                float denom = d1x[a] * d2y[b] - d1y[a] * d2x[b];
                if (fabsf(denom) > EPSF) {
                    float rpx = q1x[b] - p1x[a];
                    float rpy = q1y[b] - p1y[a];
                    float t = (rpx * d2y[b] - rpy * d2x[b]) / denom;
                    float u = (rpx * d1y[a] - rpy * d1x[a]) / denom;
                    if (t >= 0.0f && t <= 1.0f && u >= 0.0f && u <= 1.0f) {
                        vx[nv] = p1x[a] + t * d1x[a];
                        vy[nv] = p1y[a] + t * d1y[a];
                        ++nv;
                    }
                }
            }
        }

        // corners of box i inside box j
#pragma unroll
        for (int a = 0; a < 4; ++a) {
            bool ge = true, le = true;
#pragma unroll
            for (int b = 0; b < 4; ++b) {
                float cvx = p1x[a] - q1x[b];
                float cvy = p1y[a] - q1y[b];
                float cr = d2x[b] * cvy - d2y[b] * cvx;
                ge = ge && (cr >= -EPSF);
                le = le && (cr <=  EPSF);
            }
            if (ge || le) { vx[nv] = p1x[a]; vy[nv] = p1y[a]; ++nv; }
        }
        // corners of box j inside box i
#pragma unroll
        for (int b = 0; b < 4; ++b) {
            bool ge = true, le = true;
#pragma unroll
            for (int a = 0; a < 4; ++a) {
                float cvx = q1x[b] - p1x[a];
                float cvy = q1y[b] - p1y[a];
                float cr = d1x[a] * cvy - d1y[a] * cvx;
                ge = ge && (cr >= -EPSF);
                le = le && (cr <=  EPSF);
            }
            if (ge || le) { vx[nv] = q1x[b]; vy[nv] = q1y[b]; ++nv; }
        }

        float inter = 0.0f;
        if (nv >= 3) {
            float sx = 0.0f, sy = 0.0f;
            for (int k = 0; k < nv; ++k) { sx += vx[k]; sy += vy[k]; }
            float cx = sx / (float)nv;
            float cy = sy / (float)nv;
            for (int k = 0; k < nv; ++k)
                va[k] = atan2f(vy[k] - cy, vx[k] - cx);

            // stable insertion sort by angle
            for (int k = 1; k < nv; ++k) {
                float a = va[k], x = vx[k], y = vy[k];
                int m = k - 1;
                while (m >= 0 && va[m] > a) {
                    va[m + 1] = va[m]; vx[m + 1] = vx[m]; vy[m + 1] = vy[m];
                    --m;
                }
                va[m + 1] = a; vx[m + 1] = x; vy[m + 1] = y;
            }

            float s = 0.0f;
            for (int k = 0; k < nv; ++k) {
                int kn = (k + 1 == nv) ? 0 : k + 1;
                s += (vx[k] - cx) * (vy[kn] - cy) - (vy[k] - cy) * (vx[kn] - cx);
            }
            inter = 0.5f * fabsf(s);
        }

        float uni = g_area[i] + g_area[j] - inter;
        float iou = inter / fmaxf(uni, EPSF);
        if (iou > NMS_THR) {
            atomicOr(&g_mask[i * WWORDS + (j >> 6)], 1ULL << (j & 63));
        }
    }
}

// ---------------------------------------------------------------------------
// Kernel 3: sequential greedy suppression (1 warp, bitmask in registers)
// + warp-parallel compaction into the output (float32 indices, pad -1.0f)
// ---------------------------------------------------------------------------
__global__ void nms_kernel(float* __restrict__ out, int N, int out_size)
{
    int lane = threadIdx.x;  // 32 lanes, lane l owns remove-word l
    unsigned long long rem = 0ULL;

    for (int i = 0; i < N; ++i) {
        int w = i >> 6, b = i & 63;
        unsigned long long row = g_mask[i * WWORDS + lane];   // prefetchable
        unsigned long long rw  = __shfl_sync(0xffffffffu, rem, w);
        bool sup = (rw >> b) & 1ULL;
        if (!sup) rem |= row;
    }

    // kept bits for this lane's word, masked to valid range [0, N)
    unsigned long long kept = ~rem;
    int base = lane * 64;
    int nb = N - base;                  // valid bits in this word
    if (nb <= 0) kept = 0ULL;
    else if (nb < 64) kept &= (~0ULL) >> (64 - nb);

    int pc = __popcll(kept);
    // warp exclusive scan of pc
    int incl = pc;
#pragma unroll
    for (int off = 1; off < 32; off <<= 1) {
        int v = __shfl_up_sync(0xffffffffu, incl, off);
        if (lane >= off) incl += v;
    }
    int excl = incl - pc;
    int total = __shfl_sync(0xffffffffu, incl, 31);

    // each lane writes its kept indices
    unsigned long long k = kept;
    int pos = excl;
    while (k) {
        int b = __ffsll((long long)k) - 1;
        if (pos < out_size) out[pos] = (float)(base + b);
        ++pos;
        k &= k - 1ULL;
    }
    // parallel fill of -1 padding
    for (int p = total + lane; p < out_size; p += 32) out[p] = -1.0f;
}

// ---------------------------------------------------------------------------
extern "C" void kernel_launch(void* const* d_in, const int* in_sizes, int n_in,
                              void* d_out, int out_size)
{
    const float* boxes = (const float*)d_in[0];
    int N = in_sizes[0] / 5;
    if (N > MAXN) N = MAXN;
    float* out = (float*)d_out;

    {
        int total = MAXN * WWORDS;           // covers mask zeroing and N boxes
        int threads = 256;
        int blocks = (total + threads - 1) / threads;
        prep_kernel<<<blocks, threads>>>(boxes, N);
    }
    {
        long long total = (long long)N * N;
        int threads = 256;
        int blocks = (int)((total + threads - 1) / threads);
        pairgen_kernel<<<blocks, threads>>>(N);
    }
    {
        // fixed dense grid; grid-stride over the device-side pair count
        clip_kernel<<<148 * 8, 256>>>(N);
    }
    nms_kernel<<<1, 32>>>(out, N, out_size);
}

// round 5
// speedup vs baseline: 4.8740x; 2.1434x over previous
#include <cuda_runtime.h>
#include <math.h>
#include <stdint.h>

#define MAXN     2048
#define WWORDS   32          // 2048 / 64 bits
#define EPSF     1e-8f
#define NMS_THR  0.7f
#define MAXPAIRS (MAXN * MAXN / 2)

// ---- device scratch (no allocations allowed) ----
__device__ float g_cx[MAXN * 4];
__device__ float g_cy[MAXN * 4];
__device__ float g_bx[MAXN];
__device__ float g_by[MAXN];
__device__ float g_area[MAXN];
__device__ float g_rad[MAXN];
__device__ unsigned long long g_mask[MAXN * WWORDS];
__device__ unsigned long long g_rowflag[WWORDS];   // bit i: row i has >=1 edge
__device__ unsigned int g_pairs[MAXPAIRS];
__device__ int g_npairs;

// ---------------------------------------------------------------------------
// Kernel 1: zero mask/flags/count; compute corners / areas / bounding radii
// ---------------------------------------------------------------------------
__global__ void prep_kernel(const float* __restrict__ boxes, int N)
{
    int tid = blockIdx.x * blockDim.x + threadIdx.x;
    if (tid == 0) g_npairs = 0;
    if (tid < WWORDS) g_rowflag[tid] = 0ULL;
    if (tid < MAXN * WWORDS) g_mask[tid] = 0ULL;
    if (tid < N) {
        float xc = boxes[tid * 5 + 0];
        float yc = boxes[tid * 5 + 1];
        float w  = boxes[tid * 5 + 2];
        float h  = boxes[tid * 5 + 3];
        float t  = boxes[tid * 5 + 4];
        float th = t * (float)(M_PI / 180.0);
        float c = cosf(th), s = sinf(th);
        const float lx[4] = { 0.5f, -0.5f, -0.5f,  0.5f };
        const float ly[4] = { 0.5f,  0.5f, -0.5f, -0.5f };
#pragma unroll
        for (int k = 0; k < 4; ++k) {
            g_cx[tid * 4 + k] = xc + lx[k] * w * c - ly[k] * h * s;
            g_cy[tid * 4 + k] = yc + lx[k] * w * s + ly[k] * h * c;
        }
        g_bx[tid] = xc;
        g_by[tid] = yc;
        g_area[tid] = w * h;
        g_rad[tid]  = 0.5f * sqrtf(w * w + h * h);
    }
}

// ---------------------------------------------------------------------------
// Kernel 2a: bounding-circle pre-filter -> dense worklist of candidate pairs
// ---------------------------------------------------------------------------
__global__ void pairgen_kernel(int N)
{
    long long tid = (long long)blockIdx.x * blockDim.x + threadIdx.x;
    int lane = threadIdx.x & 31;

    bool surv = false;
    int i = 0, j = 0;
    if (tid < (long long)N * N) {
        i = (int)(tid / N);
        j = (int)(tid - (long long)i * N);
        if (j > i) {
            float dx = g_bx[i] - g_bx[j];
            float dy = g_by[i] - g_by[j];
            float rr = g_rad[i] + g_rad[j];
            surv = (dx * dx + dy * dy <= rr * rr);
        }
    }

    unsigned m = __ballot_sync(0xffffffffu, surv);
    if (m) {
        int cnt = __popc(m);
        int leader = __ffs(m) - 1;
        int base = 0;
        if (lane == leader) base = atomicAdd(&g_npairs, cnt);
        base = __shfl_sync(0xffffffffu, base, leader);
        if (surv) {
            int pos = base + __popc(m & ((1u << lane) - 1u));
            g_pairs[pos] = ((unsigned)i << 11) | (unsigned)j;
        }
    }
}

// ---------------------------------------------------------------------------
// Kernel 2b: dense polygon-clip IoU over the worklist -> suppression bitmask
// + row-nonempty flag bitmap. Math byte-identical to the reference path.
// ---------------------------------------------------------------------------
__global__ void clip_kernel(int N)
{
    int np = g_npairs;
    int stride = gridDim.x * blockDim.x;
    for (int idx = blockIdx.x * blockDim.x + threadIdx.x; idx < np; idx += stride) {
        unsigned pr = g_pairs[idx];
        int i = (int)(pr >> 11);
        int j = (int)(pr & 0x7FFu);

        float p1x[4], p1y[4], q1x[4], q1y[4];
#pragma unroll
        for (int k = 0; k < 4; ++k) {
            p1x[k] = g_cx[i * 4 + k];  p1y[k] = g_cy[i * 4 + k];
            q1x[k] = g_cx[j * 4 + k];  q1y[k] = g_cy[j * 4 + k];
        }
        float d1x[4], d1y[4], d2x[4], d2y[4];
#pragma unroll
        for (int k = 0; k < 4; ++k) {
            int kn = (k + 1) & 3;
            d1x[k] = p1x[kn] - p1x[k];  d1y[k] = p1y[kn] - p1y[k];
            d2x[k] = q1x[kn] - q1x[k];  d2y[k] = q1y[kn] - q1y[k];
        }

        float vx[24], vy[24], va[24];
        int nv = 0;

        // 16 edge-edge intersections
#pragma unroll
        for (int a = 0; a < 4; ++a) {
#pragma unroll
            for (int b = 0; b < 4; ++b) {
                float denom = d1x[a] * d2y[b] - d1y[a] * d2x[b];
                if (fabsf(denom) > EPSF) {
                    float rpx = q1x[b] - p1x[a];
                    float rpy = q1y[b] - p1y[a];
                    float t = (rpx * d2y[b] - rpy * d2x[b]) / denom;
                    float u = (rpx * d1y[a] - rpy * d1x[a]) / denom;
                    if (t >= 0.0f && t <= 1.0f && u >= 0.0f && u <= 1.0f) {
                        vx[nv] = p1x[a] + t * d1x[a];
                        vy[nv] = p1y[a] + t * d1y[a];
                        ++nv;
                    }
                }
            }
        }

        // corners of box i inside box j
#pragma unroll
        for (int a = 0; a < 4; ++a) {
            bool ge = true, le = true;
#pragma unroll
            for (int b = 0; b < 4; ++b) {
                float cvx = p1x[a] - q1x[b];
                float cvy = p1y[a] - q1y[b];
                float cr = d2x[b] * cvy - d2y[b] * cvx;
                ge = ge && (cr >= -EPSF);
                le = le && (cr <=  EPSF);
            }
            if (ge || le) { vx[nv] = p1x[a]; vy[nv] = p1y[a]; ++nv; }
        }
        // corners of box j inside box i
#pragma unroll
        for (int b = 0; b < 4; ++b) {
            bool ge = true, le = true;
#pragma unroll
            for (int a = 0; a < 4; ++a) {
                float cvx = q1x[b] - p1x[a];
                float cvy = q1y[b] - p1y[a];
                float cr = d1x[a] * cvy - d1y[a] * cvx;
                ge = ge && (cr >= -EPSF);
                le = le && (cr <=  EPSF);
            }
            if (ge || le) { vx[nv] = q1x[b]; vy[nv] = q1y[b]; ++nv; }
        }

        float inter = 0.0f;
        if (nv >= 3) {
            float sx = 0.0f, sy = 0.0f;
            for (int k = 0; k < nv; ++k) { sx += vx[k]; sy += vy[k]; }
            float cx = sx / (float)nv;
            float cy = sy / (float)nv;
            for (int k = 0; k < nv; ++k)
                va[k] = atan2f(vy[k] - cy, vx[k] - cx);

            // stable insertion sort by angle
            for (int k = 1; k < nv; ++k) {
                float a = va[k], x = vx[k], y = vy[k];
                int m = k - 1;
                while (m >= 0 && va[m] > a) {
                    va[m + 1] = va[m]; vx[m + 1] = vx[m]; vy[m + 1] = vy[m];
                    --m;
                }
                va[m + 1] = a; vx[m + 1] = x; vy[m + 1] = y;
            }

            float s = 0.0f;
            for (int k = 0; k < nv; ++k) {
                int kn = (k + 1 == nv) ? 0 : k + 1;
                s += (vx[k] - cx) * (vy[kn] - cy) - (vy[k] - cy) * (vx[kn] - cx);
            }
            inter = 0.5f * fabsf(s);
        }

        float uni = g_area[i] + g_area[j] - inter;
        float iou = inter / fmaxf(uni, EPSF);
        if (iou > NMS_THR) {
            atomicOr(&g_mask[i * WWORDS + (j >> 6)], 1ULL << (j & 63));
            atomicOr(&g_rowflag[i >> 6], 1ULL << (i & 63));
        }
    }
}

// ---------------------------------------------------------------------------
// Kernel 3: greedy suppression visiting ONLY nonempty rows (ascending i),
// row-OR parallel across the warp; then warp-parallel compaction.
// ---------------------------------------------------------------------------
__global__ void nms_kernel(float* __restrict__ out, int N, int out_size)
{
    int lane = threadIdx.x;
    __shared__ unsigned long long rem[WWORDS];
    rem[lane] = 0ULL;
    __syncwarp();

    for (int w = 0; w < WWORDS; ++w) {
        unsigned long long flag = g_rowflag[w];   // same value in all lanes
        while (flag) {
            int b = __ffsll((long long)flag) - 1;
            flag &= flag - 1ULL;
            int i = w * 64 + b;
            unsigned long long rw = rem[i >> 6];  // broadcast smem read
            if (!((rw >> (i & 63)) & 1ULL)) {
                rem[lane] |= g_mask[i * WWORDS + lane];   // parallel row OR
            }
            __syncwarp();
        }
    }

    // kept bits for this lane's word, masked to valid range [0, N)
    unsigned long long kept = ~rem[lane];
    int base = lane * 64;
    int nb = N - base;
    if (nb <= 0) kept = 0ULL;
    else if (nb < 64) kept &= (~0ULL) >> (64 - nb);

    int pc = __popcll(kept);
    int incl = pc;
#pragma unroll
    for (int off = 1; off < 32; off <<= 1) {
        int v = __shfl_up_sync(0xffffffffu, incl, off);
        if (lane >= off) incl += v;
    }
    int excl = incl - pc;
    int total = __shfl_sync(0xffffffffu, incl, 31);

    unsigned long long k = kept;
    int pos = excl;
    while (k) {
        int b = __ffsll((long long)k) - 1;
        if (pos < out_size) out[pos] = (float)(base + b);
        ++pos;
        k &= k - 1ULL;
    }
    for (int p = total + lane; p < out_size; p += 32) out[p] = -1.0f;
}

// ---------------------------------------------------------------------------
extern "C" void kernel_launch(void* const* d_in, const int* in_sizes, int n_in,
                              void* d_out, int out_size)
{
    const float* boxes = (const float*)d_in[0];
    int N = in_sizes[0] / 5;
    if (N > MAXN) N = MAXN;
    float* out = (float*)d_out;

    {
        int total = MAXN * WWORDS;
        int threads = 256;
        int blocks = (total + threads - 1) / threads;
        prep_kernel<<<blocks, threads>>>(boxes, N);
    }
    {
        long long total = (long long)N * N;
        int threads = 256;
        int blocks = (int)((total + threads - 1) / threads);
        pairgen_kernel<<<blocks, threads>>>(N);
    }
    clip_kernel<<<148 * 8, 256>>>(N);
    nms_kernel<<<1, 32>>>(out, N, out_size);
}

// round 6
// speedup vs baseline: 6.1264x; 1.2570x over previous
#include <cuda_runtime.h>
#include <math.h>
#include <stdint.h>

#define MAXN     2048
#define WWORDS   32          // 2048 / 64 bits
#define EPSF     1e-8f
#define NMS_THR  0.7f
#define MAXPAIRS (MAXN * MAXN / 2)
#define NMS_T    1024
#define PREF_ROWS 128

// ---- device scratch (no allocations allowed; .bss zero-initialized) ----
__device__ float4 g_box[MAXN];        // bx, by, rad, area
__device__ float4 g_crn[MAXN * 2];    // (x0,y0,x1,y1), (x2,y2,x3,y3)
__device__ unsigned long long g_mask[MAXN * WWORDS];   // self-cleaned by nms
__device__ unsigned long long g_rowflag[WWORDS];       // self-cleaned by nms
__device__ unsigned int g_pairs[MAXPAIRS];
__device__ int g_npairs;

// ---------------------------------------------------------------------------
// Kernel 1: per-box data (corners, circle, area). Mask NOT zeroed here:
// it starts zero (.bss) and nms_kernel re-zeroes the rows it dirties.
// ---------------------------------------------------------------------------
__global__ void prep_kernel(const float* __restrict__ boxes, int N)
{
    int tid = blockIdx.x * blockDim.x + threadIdx.x;
    if (tid == 0) g_npairs = 0;
    if (tid < N) {
        float xc = boxes[tid * 5 + 0];
        float yc = boxes[tid * 5 + 1];
        float w  = boxes[tid * 5 + 2];
        float h  = boxes[tid * 5 + 3];
        float t  = boxes[tid * 5 + 4];
        float th = t * (float)(M_PI / 180.0);
        float c = cosf(th), s = sinf(th);
        const float lx[4] = { 0.5f, -0.5f, -0.5f,  0.5f };
        const float ly[4] = { 0.5f,  0.5f, -0.5f, -0.5f };
        float cx[4], cy[4];
#pragma unroll
        for (int k = 0; k < 4; ++k) {
            cx[k] = xc + lx[k] * w * c - ly[k] * h * s;
            cy[k] = yc + lx[k] * w * s + ly[k] * h * c;
        }
        g_crn[tid * 2 + 0] = make_float4(cx[0], cy[0], cx[1], cy[1]);
        g_crn[tid * 2 + 1] = make_float4(cx[2], cy[2], cx[3], cy[3]);
        g_box[tid] = make_float4(xc, yc, 0.5f * sqrtf(w * w + h * h), w * h);
    }
}

// ---------------------------------------------------------------------------
// Kernel 2a: bounding-circle pre-filter over folded triangle -> worklist
// ---------------------------------------------------------------------------
__global__ void pairgen_kernel(int N, int M)   // M = N rounded up to even
{
    int t = blockIdx.x * blockDim.x + threadIdx.x;
    int lane = threadIdx.x & 31;
    int total = M * (M >> 1);

    bool surv = false;
    int i = 0, j = 0;
    if (t < total) {
        int i0 = t / M;
        int jj = t - i0 * M;
        if (jj > i0)      { i = i0;         j = jj; }
        else if (jj < i0) { i = M - 1 - i0; j = M - 1 - jj; }
        else              { i = -1; }
        if (i >= 0 && j < N && i < N) {
            float4 bi = g_box[i];
            float4 bj = g_box[j];
            float dx = bi.x - bj.x;
            float dy = bi.y - bj.y;
            float rr = bi.z + bj.z;
            surv = (dx * dx + dy * dy <= rr * rr);
        }
    }

    unsigned m = __ballot_sync(0xffffffffu, surv);
    if (m) {
        int cnt = __popc(m);
        int leader = __ffs(m) - 1;
        int base = 0;
        if (lane == leader) base = atomicAdd(&g_npairs, cnt);
        base = __shfl_sync(0xffffffffu, base, leader);
        if (surv) {
            int pos = base + __popc(m & ((1u << lane) - 1u));
            g_pairs[pos] = ((unsigned)i << 11) | (unsigned)j;
        }
    }
}

// ---------------------------------------------------------------------------
// Kernel 2b: dense polygon-clip IoU over the worklist -> suppression bitmask
// + row-nonempty flags. Math byte-identical to the reference path.
// ---------------------------------------------------------------------------
__global__ void clip_kernel(int N)
{
    int np = g_npairs;
    int stride = gridDim.x * blockDim.x;
    for (int idx = blockIdx.x * blockDim.x + threadIdx.x; idx < np; idx += stride) {
        unsigned pr = g_pairs[idx];
        int i = (int)(pr >> 11);
        int j = (int)(pr & 0x7FFu);

        float p1x[4], p1y[4], q1x[4], q1y[4];
        {
            float4 a0 = g_crn[i * 2 + 0], a1 = g_crn[i * 2 + 1];
            float4 b0 = g_crn[j * 2 + 0], b1 = g_crn[j * 2 + 1];
            p1x[0] = a0.x; p1y[0] = a0.y; p1x[1] = a0.z; p1y[1] = a0.w;
            p1x[2] = a1.x; p1y[2] = a1.y; p1x[3] = a1.z; p1y[3] = a1.w;
            q1x[0] = b0.x; q1y[0] = b0.y; q1x[1] = b0.z; q1y[1] = b0.w;
            q1x[2] = b1.x; q1y[2] = b1.y; q1x[3] = b1.z; q1y[3] = b1.w;
        }
        float d1x[4], d1y[4], d2x[4], d2y[4];
#pragma unroll
        for (int k = 0; k < 4; ++k) {
            int kn = (k + 1) & 3;
            d1x[k] = p1x[kn] - p1x[k];  d1y[k] = p1y[kn] - p1y[k];
            d2x[k] = q1x[kn] - q1x[k];  d2y[k] = q1y[kn] - q1y[k];
        }

        float vx[24], vy[24], va[24];
        int nv = 0;

        // 16 edge-edge intersections
#pragma unroll
        for (int a = 0; a < 4; ++a) {
#pragma unroll
            for (int b = 0; b < 4; ++b) {
                float denom = d1x[a] * d2y[b] - d1y[a] * d2x[b];
                if (fabsf(denom) > EPSF) {
                    float rpx = q1x[b] - p1x[a];
                    float rpy = q1y[b] - p1y[a];
                    float t = (rpx * d2y[b] - rpy * d2x[b]) / denom;
                    float u = (rpx * d1y[a] - rpy * d1x[a]) / denom;
                    if (t >= 0.0f && t <= 1.0f && u >= 0.0f && u <= 1.0f) {
                        vx[nv] = p1x[a] + t * d1x[a];
                        vy[nv] = p1y[a] + t * d1y[a];
                        ++nv;
                    }
                }
            }
        }

        // corners of box i inside box j
#pragma unroll
        for (int a = 0; a < 4; ++a) {
            bool ge = true, le = true;
#pragma unroll
            for (int b = 0; b < 4; ++b) {
                float cvx = p1x[a] - q1x[b];
                float cvy = p1y[a] - q1y[b];
                float cr = d2x[b] * cvy - d2y[b] * cvx;
                ge = ge && (cr >= -EPSF);
                le = le && (cr <=  EPSF);
            }
            if (ge || le) { vx[nv] = p1x[a]; vy[nv] = p1y[a]; ++nv; }
        }
        // corners of box j inside box i
#pragma unroll
        for (int b = 0; b < 4; ++b) {
            bool ge = true, le = true;
#pragma unroll
            for (int a = 0; a < 4; ++a) {
                float cvx = q1x[b] - p1x[a];
                float cvy = q1y[b] - p1y[a];
                float cr = d1x[a] * cvy - d1y[a] * cvx;
                ge = ge && (cr >= -EPSF);
                le = le && (cr <=  EPSF);
            }
            if (ge || le) { vx[nv] = q1x[b]; vy[nv] = q1y[b]; ++nv; }
        }

        float inter = 0.0f;
        if (nv >= 3) {
            float sx = 0.0f, sy = 0.0f;
            for (int k = 0; k < nv; ++k) { sx += vx[k]; sy += vy[k]; }
            float cx = sx / (float)nv;
            float cy = sy / (float)nv;
            for (int k = 0; k < nv; ++k)
                va[k] = atan2f(vy[k] - cy, vx[k] - cx);

            // stable insertion sort by angle
            for (int k = 1; k < nv; ++k) {
                float a = va[k], x = vx[k], y = vy[k];
                int m = k - 1;
                while (m >= 0 && va[m] > a) {
                    va[m + 1] = va[m]; vx[m + 1] = vx[m]; vy[m + 1] = vy[m];
                    --m;
                }
                va[m + 1] = a; vx[m + 1] = x; vy[m + 1] = y;
            }

            float s = 0.0f;
            for (int k = 0; k < nv; ++k) {
                int kn = (k + 1 == nv) ? 0 : k + 1;
                s += (vx[k] - cx) * (vy[kn] - cy) - (vy[k] - cy) * (vx[kn] - cx);
            }
            inter = 0.5f * fabsf(s);
        }

        float ai = g_box[i].w, aj = g_box[j].w;
        float uni = ai + aj - inter;
        float iou = inter / fmaxf(uni, EPSF);
        if (iou > NMS_THR) {
            atomicOr(&g_mask[i * WWORDS + (j >> 6)], 1ULL << (j & 63));
            atomicOr(&g_rowflag[i >> 6], 1ULL << (i & 63));
        }
    }
}

// ---------------------------------------------------------------------------
// Kernel 3: greedy suppression over flagged rows only. 1024 threads:
// parallel row prefetch to smem -> warp-0 serial greedy over smem ->
// block-wide compaction. Self-cleans g_mask / g_rowflag for the next replay.
// ---------------------------------------------------------------------------
__global__ void __launch_bounds__(NMS_T)
nms_kernel(float* __restrict__ out, int N, int out_size)
{
    __shared__ unsigned long long s_flag[WWORDS];
    __shared__ unsigned long long s_rem[WWORDS];
    __shared__ unsigned long long s_kept[WWORDS];
    __shared__ int s_wexcl[WWORDS + 1];
    __shared__ short s_rowlist[MAXN];
    __shared__ int s_nrows;
    __shared__ unsigned long long s_rowdata[PREF_ROWS][WWORDS];   // 32 KB

    int tid = threadIdx.x;
    int lane = tid & 31, wid = tid >> 5;

    if (tid < WWORDS) { s_flag[tid] = g_rowflag[tid]; s_rem[tid] = 0ULL; }
    __syncthreads();

    // exclusive scan of per-word flag popcounts (warp 0)
    if (wid == 0) {
        int pc = __popcll(s_flag[lane]);
        int incl = pc;
#pragma unroll
        for (int off = 1; off < 32; off <<= 1) {
            int v = __shfl_up_sync(0xffffffffu, incl, off);
            if (lane >= off) incl += v;
        }
        s_wexcl[lane] = incl - pc;
        if (lane == 31) s_nrows = incl;
    }
    __syncthreads();
    int nrows = s_nrows;

    // scatter flagged row indices (ascending) into s_rowlist
    for (int p = tid; p < MAXN; p += NMS_T) {
        int w = p >> 6, b = p & 63;
        unsigned long long f = s_flag[w];
        if ((f >> b) & 1ULL) {
            int pos = s_wexcl[w] + __popcll(f & ((1ULL << b) - 1ULL));
            s_rowlist[pos] = (short)p;
        }
    }
    __syncthreads();

    // parallel prefetch of flagged rows (first PREF_ROWS) into smem
    int npf = nrows < PREF_ROWS ? nrows : PREF_ROWS;
    for (int idx = tid; idx < npf * WWORDS; idx += NMS_T) {
        int r = idx >> 5, w = idx & 31;
        s_rowdata[r][w] = g_mask[(int)s_rowlist[r] * WWORDS + w];
    }
    __syncthreads();

    // serial greedy (warp 0) over smem rows
    if (wid == 0) {
        for (int r = 0; r < nrows; ++r) {
            int i = (int)s_rowlist[r];
            if (!((s_rem[i >> 6] >> (i & 63)) & 1ULL)) {
                unsigned long long row = (r < PREF_ROWS)
                    ? s_rowdata[r][lane]
                    : g_mask[i * WWORDS + lane];
                s_rem[lane] |= row;
            }
            __syncwarp();
        }
        // kept bits + exclusive scan of per-word counts
        unsigned long long kept = ~s_rem[lane];
        int base = lane * 64;
        int nb = N - base;
        if (nb <= 0) kept = 0ULL;
        else if (nb < 64) kept &= (~0ULL) >> (64 - nb);
        s_kept[lane] = kept;
        int pc = __popcll(kept);
        int incl = pc;
#pragma unroll
        for (int off = 1; off < 32; off <<= 1) {
            int v = __shfl_up_sync(0xffffffffu, incl, off);
            if (lane >= off) incl += v;
        }
        s_wexcl[lane] = incl - pc;
        if (lane == 31) s_wexcl[32] = incl;
    }
    __syncthreads();

    // self-clean dirty mask rows + rowflag (for next graph replay)
    for (int idx = tid; idx < nrows * WWORDS; idx += NMS_T)
        g_mask[(int)s_rowlist[idx >> 5] * WWORDS + (idx & 31)] = 0ULL;
    if (tid < WWORDS) g_rowflag[tid] = 0ULL;

    // block-wide compaction
    int total = s_wexcl[32];
    for (int p = tid; p < MAXN; p += NMS_T) {
        int w = p >> 6, b = p & 63;
        unsigned long long k = s_kept[w];
        if ((k >> b) & 1ULL) {
            int pos = s_wexcl[w] + __popcll(k & ((1ULL << b) - 1ULL));
            if (pos < out_size) out[pos] = (float)p;
        }
    }
    for (int p = total + tid; p < out_size; p += NMS_T) out[p] = -1.0f;
}

// ---------------------------------------------------------------------------
extern "C" void kernel_launch(void* const* d_in, const int* in_sizes, int n_in,
                              void* d_out, int out_size)
{
    const float* boxes = (const float*)d_in[0];
    int N = in_sizes[0] / 5;
    if (N > MAXN) N = MAXN;
    float* out = (float*)d_out;

    {
        int threads = 256;
        int blocks = (N + threads - 1) / threads;
        prep_kernel<<<blocks, threads>>>(boxes, N);
    }
    {
        int M = (N + 1) & ~1;                 // even
        int total = M * (M >> 1);
        int threads = 256;
        int blocks = (total + threads - 1) / threads;
        pairgen_kernel<<<blocks, threads>>>(N, M);
    }
    clip_kernel<<<148 * 8, 256>>>(N);
    nms_kernel<<<1, NMS_T>>>(out, N, out_size);
}

// round 7
// speedup vs baseline: 9.9063x; 1.6170x over previous
#include <cuda_runtime.h>
#include <math.h>
#include <stdint.h>

#define MAXN     2048
#define WWORDS   32          // 2048 / 64 bits
#define EPSF     1e-8f
#define NMS_THR  0.7f
#define MAXPAIRS (MAXN * MAXN / 2)
#define NMS_T    1024
#define PREF_ROWS 128

// ---- device scratch (no allocations allowed; .bss zero-initialized) ----
__device__ float4 g_box[MAXN];        // bx, by, rad, area
__device__ float4 g_crn[MAXN * 2];    // (x0,y0,x1,y1), (x2,y2,x3,y3)
__device__ unsigned long long g_mask[MAXN * WWORDS];   // self-cleaned by nms
__device__ unsigned long long g_rowflag[WWORDS];       // self-cleaned by nms
__device__ unsigned int g_pairs[MAXPAIRS];
__device__ int g_npairs;

// ---------------------------------------------------------------------------
// Kernel 1: per-box data (corners, circle, area). Mask NOT zeroed here:
// starts zero (.bss); nms_kernel re-zeroes exactly the rows it dirties.
// ---------------------------------------------------------------------------
__global__ void prep_kernel(const float* __restrict__ boxes, int N)
{
    int tid = blockIdx.x * blockDim.x + threadIdx.x;
    if (tid == 0) g_npairs = 0;
    if (tid < N) {
        float xc = boxes[tid * 5 + 0];
        float yc = boxes[tid * 5 + 1];
        float w  = boxes[tid * 5 + 2];
        float h  = boxes[tid * 5 + 3];
        float t  = boxes[tid * 5 + 4];
        float th = t * (float)(M_PI / 180.0);
        float c = cosf(th), s = sinf(th);
        const float lx[4] = { 0.5f, -0.5f, -0.5f,  0.5f };
        const float ly[4] = { 0.5f,  0.5f, -0.5f, -0.5f };
        float cx[4], cy[4];
#pragma unroll
        for (int k = 0; k < 4; ++k) {
            cx[k] = xc + lx[k] * w * c - ly[k] * h * s;
            cy[k] = yc + lx[k] * w * s + ly[k] * h * c;
        }
        g_crn[tid * 2 + 0] = make_float4(cx[0], cy[0], cx[1], cy[1]);
        g_crn[tid * 2 + 1] = make_float4(cx[2], cy[2], cx[3], cy[3]);
        g_box[tid] = make_float4(xc, yc, 0.5f * sqrtf(w * w + h * h), w * h);
    }
}

// ---------------------------------------------------------------------------
// Kernel 2a: pre-filter over folded triangle -> worklist.
// Filters: bounding-circle contact AND exact area-ratio IoU upper bound.
//   inter <= min(ai,aj)  and  iou monotone in inter
//   => iou <= min / max(ai+aj-min, EPS).  Skip if that bound <= 0.7.
// 2D grid: blockIdx.y = i0 in [0, M/2); x covers jj in [0, M).
// ---------------------------------------------------------------------------
__global__ void pairgen_kernel(int N, int M)   // M = N rounded up to even
{
    int jj = blockIdx.x * blockDim.x + threadIdx.x;
    int i0 = blockIdx.y;
    int lane = threadIdx.x & 31;

    bool surv = false;
    int i = 0, j = 0;
    if (jj < M) {
        if (jj > i0)      { i = i0;         j = jj; }
        else if (jj < i0) { i = M - 1 - i0; j = M - 1 - jj; }
        else              { i = -1; }
        if (i >= 0 && i < N && j < N) {
            float4 bi = g_box[i];
            float4 bj = g_box[j];
            float dx = bi.x - bj.x;
            float dy = bi.y - bj.y;
            float rr = bi.z + bj.z;
            if (dx * dx + dy * dy <= rr * rr) {
                float mn = fminf(bi.w, bj.w);
                float bound = mn / fmaxf(bi.w + bj.w - mn, EPSF);
                surv = (bound > NMS_THR);
            }
        }
    }

    unsigned m = __ballot_sync(0xffffffffu, surv);
    if (m) {
        int cnt = __popc(m);
        int leader = __ffs(m) - 1;
        int base = 0;
        if (lane == leader) base = atomicAdd(&g_npairs, cnt);
        base = __shfl_sync(0xffffffffu, base, leader);
        if (surv) {
            int pos = base + __popc(m & ((1u << lane) - 1u));
            g_pairs[pos] = ((unsigned)i << 11) | (unsigned)j;
        }
    }
}

// ---------------------------------------------------------------------------
// Kernel 2b: dense polygon-clip IoU over the worklist -> suppression bitmask
// + row-nonempty flags. Math byte-identical to the reference path.
// ---------------------------------------------------------------------------
__global__ void clip_kernel(int N)
{
    int np = g_npairs;
    int stride = gridDim.x * blockDim.x;
    for (int idx = blockIdx.x * blockDim.x + threadIdx.x; idx < np; idx += stride) {
        unsigned pr = g_pairs[idx];
        int i = (int)(pr >> 11);
        int j = (int)(pr & 0x7FFu);

        float p1x[4], p1y[4], q1x[4], q1y[4];
        {
            float4 a0 = g_crn[i * 2 + 0], a1 = g_crn[i * 2 + 1];
            float4 b0 = g_crn[j * 2 + 0], b1 = g_crn[j * 2 + 1];
            p1x[0] = a0.x; p1y[0] = a0.y; p1x[1] = a0.z; p1y[1] = a0.w;
            p1x[2] = a1.x; p1y[2] = a1.y; p1x[3] = a1.z; p1y[3] = a1.w;
            q1x[0] = b0.x; q1y[0] = b0.y; q1x[1] = b0.z; q1y[1] = b0.w;
            q1x[2] = b1.x; q1y[2] = b1.y; q1x[3] = b1.z; q1y[3] = b1.w;
        }
        float d1x[4], d1y[4], d2x[4], d2y[4];
#pragma unroll
        for (int k = 0; k < 4; ++k) {
            int kn = (k + 1) & 3;
            d1x[k] = p1x[kn] - p1x[k];  d1y[k] = p1y[kn] - p1y[k];
            d2x[k] = q1x[kn] - q1x[k];  d2y[k] = q1y[kn] - q1y[k];
        }

        float vx[24], vy[24], va[24];
        int nv = 0;

        // 16 edge-edge intersections
#pragma unroll
        for (int a = 0; a < 4; ++a) {
#pragma unroll
            for (int b = 0; b < 4; ++b) {
                float denom = d1x[a] * d2y[b] - d1y[a] * d2x[b];
                if (fabsf(denom) > EPSF) {
                    float rpx = q1x[b] - p1x[a];
                    float rpy = q1y[b] - p1y[a];
                    float t = (rpx * d2y[b] - rpy * d2x[b]) / denom;
                    float u = (rpx * d1y[a] - rpy * d1x[a]) / denom;
                    if (t >= 0.0f && t <= 1.0f && u >= 0.0f && u <= 1.0f) {
                        vx[nv] = p1x[a] + t * d1x[a];
                        vy[nv] = p1y[a] + t * d1y[a];
                        ++nv;
                    }
                }
            }
        }

        // corners of box i inside box j
#pragma unroll
        for (int a = 0; a < 4; ++a) {
            bool ge = true, le = true;
#pragma unroll
            for (int b = 0; b < 4; ++b) {
                float cvx = p1x[a] - q1x[b];
                float cvy = p1y[a] - q1y[b];
                float cr = d2x[b] * cvy - d2y[b] * cvx;
                ge = ge && (cr >= -EPSF);
                le = le && (cr <=  EPSF);
            }
            if (ge || le) { vx[nv] = p1x[a]; vy[nv] = p1y[a]; ++nv; }
        }
        // corners of box j inside box i
#pragma unroll
        for (int b = 0; b < 4; ++b) {
            bool ge = true, le = true;
#pragma unroll
            for (int a = 0; a < 4; ++a) {
                float cvx = q1x[b] - p1x[a];
                float cvy = q1y[b] - p1y[a];
                float cr = d1x[a] * cvy - d1y[a] * cvx;
                ge = ge && (cr >= -EPSF);
                le = le && (cr <=  EPSF);
            }
            if (ge || le) { vx[nv] = q1x[b]; vy[nv] = q1y[b]; ++nv; }
        }

        float inter = 0.0f;
        if (nv >= 3) {
            float sx = 0.0f, sy = 0.0f;
            for (int k = 0; k < nv; ++k) { sx += vx[k]; sy += vy[k]; }
            float cx = sx / (float)nv;
            float cy = sy / (float)nv;
            for (int k = 0; k < nv; ++k)
                va[k] = atan2f(vy[k] - cy, vx[k] - cx);

            // stable insertion sort by angle
            for (int k = 1; k < nv; ++k) {
                float a = va[k], x = vx[k], y = vy[k];
                int m = k - 1;
                while (m >= 0 && va[m] > a) {
                    va[m + 1] = va[m]; vx[m + 1] = vx[m]; vy[m + 1] = vy[m];
                    --m;
                }
                va[m + 1] = a; vx[m + 1] = x; vy[m + 1] = y;
            }

            float s = 0.0f;
            for (int k = 0; k < nv; ++k) {
                int kn = (k + 1 == nv) ? 0 : k + 1;
                s += (vx[k] - cx) * (vy[kn] - cy) - (vy[k] - cy) * (vx[kn] - cx);
            }
            inter = 0.5f * fabsf(s);
        }

        float ai = g_box[i].w, aj = g_box[j].w;
        float uni = ai + aj - inter;
        float iou = inter / fmaxf(uni, EPSF);
        if (iou > NMS_THR) {
            atomicOr(&g_mask[i * WWORDS + (j >> 6)], 1ULL << (j & 63));
            atomicOr(&g_rowflag[i >> 6], 1ULL << (i & 63));
        }
    }
}

// ---------------------------------------------------------------------------
// Kernel 3: greedy suppression over flagged rows only. 1024 threads:
// parallel row prefetch to smem -> warp-0 serial greedy over smem ->
// block-wide compaction. Self-cleans g_mask / g_rowflag for the next replay.
// ---------------------------------------------------------------------------
__global__ void __launch_bounds__(NMS_T)
nms_kernel(float* __restrict__ out, int N, int out_size)
{
    __shared__ unsigned long long s_flag[WWORDS];
    __shared__ unsigned long long s_rem[WWORDS];
    __shared__ unsigned long long s_kept[WWORDS];
    __shared__ int s_wexcl[WWORDS + 1];
    __shared__ short s_rowlist[MAXN];
    __shared__ int s_nrows;
    __shared__ unsigned long long s_rowdata[PREF_ROWS][WWORDS];   // 32 KB

    int tid = threadIdx.x;
    int lane = tid & 31, wid = tid >> 5;

    if (tid < WWORDS) { s_flag[tid] = g_rowflag[tid]; s_rem[tid] = 0ULL; }
    __syncthreads();

    // exclusive scan of per-word flag popcounts (warp 0)
    if (wid == 0) {
        int pc = __popcll(s_flag[lane]);
        int incl = pc;
#pragma unroll
        for (int off = 1; off < 32; off <<= 1) {
            int v = __shfl_up_sync(0xffffffffu, incl, off);
            if (lane >= off) incl += v;
        }
        s_wexcl[lane] = incl - pc;
        if (lane == 31) s_nrows = incl;
    }
    __syncthreads();
    int nrows = s_nrows;

    // scatter flagged row indices (ascending) into s_rowlist
    for (int p = tid; p < MAXN; p += NMS_T) {
        int w = p >> 6, b = p & 63;
        unsigned long long f = s_flag[w];
        if ((f >> b) & 1ULL) {
            int pos = s_wexcl[w] + __popcll(f & ((1ULL << b) - 1ULL));
            s_rowlist[pos] = (short)p;
        }
    }
    __syncthreads();

    // parallel prefetch of flagged rows (first PREF_ROWS) into smem
    int npf = nrows < PREF_ROWS ? nrows : PREF_ROWS;
    for (int idx = tid; idx < npf * WWORDS; idx += NMS_T) {
        int r = idx >> 5, w = idx & 31;
        s_rowdata[r][w] = g_mask[(int)s_rowlist[r] * WWORDS + w];
    }
    __syncthreads();

    // serial greedy (warp 0) over smem rows
    if (wid == 0) {
        for (int r = 0; r < nrows; ++r) {
            int i = (int)s_rowlist[r];
            if (!((s_rem[i >> 6] >> (i & 63)) & 1ULL)) {
                unsigned long long row = (r < PREF_ROWS)
                    ? s_rowdata[r][lane]
                    : g_mask[i * WWORDS + lane];
                s_rem[lane] |= row;
            }
            __syncwarp();
        }
        // kept bits + exclusive scan of per-word counts
        unsigned long long kept = ~s_rem[lane];
        int base = lane * 64;
        int nb = N - base;
        if (nb <= 0) kept = 0ULL;
        else if (nb < 64) kept &= (~0ULL) >> (64 - nb);
        s_kept[lane] = kept;
        int pc = __popcll(kept);
        int incl = pc;
#pragma unroll
        for (int off = 1; off < 32; off <<= 1) {
            int v = __shfl_up_sync(0xffffffffu, incl, off);
            if (lane >= off) incl += v;
        }
        s_wexcl[lane] = incl - pc;
        if (lane == 31) s_wexcl[32] = incl;
    }
    __syncthreads();

    // self-clean dirty mask rows + rowflag (for next graph replay)
    for (int idx = tid; idx < nrows * WWORDS; idx += NMS_T)
        g_mask[(int)s_rowlist[idx >> 5] * WWORDS + (idx & 31)] = 0ULL;
    if (tid < WWORDS) g_rowflag[tid] = 0ULL;

    // block-wide compaction
    int total = s_wexcl[32];
    for (int p = tid; p < MAXN; p += NMS_T) {
        int w = p >> 6, b = p & 63;
        unsigned long long k = s_kept[w];
        if ((k >> b) & 1ULL) {
            int pos = s_wexcl[w] + __popcll(k & ((1ULL << b) - 1ULL));
            if (pos < out_size) out[pos] = (float)p;
        }
    }
    for (int p = total + tid; p < out_size; p += NMS_T) out[p] = -1.0f;
}

// ---------------------------------------------------------------------------
extern "C" void kernel_launch(void* const* d_in, const int* in_sizes, int n_in,
                              void* d_out, int out_size)
{
    const float* boxes = (const float*)d_in[0];
    int N = in_sizes[0] / 5;
    if (N > MAXN) N = MAXN;
    float* out = (float*)d_out;

    {
        int threads = 256;
        int blocks = (N + threads - 1) / threads;
        prep_kernel<<<blocks, threads>>>(boxes, N);
    }
    {
        int M = (N + 1) & ~1;                 // even
        dim3 grid((M + 255) / 256, M >> 1);
        pairgen_kernel<<<grid, 256>>>(N, M);
    }
    clip_kernel<<<148 * 4, 256>>>(N);
    nms_kernel<<<1, NMS_T>>>(out, N, out_size);
}

// round 8
// speedup vs baseline: 11.0115x; 1.1116x over previous
#include <cuda_runtime.h>
#include <math.h>
#include <stdint.h>

#define MAXN     2048
#define WWORDS   32          // 2048 / 64 bits
#define EPSF     1e-8f
#define NMS_THR  0.7f
#define MAXPAIRS (MAXN * MAXN / 2)
#define CLIP_BLOCKS (148 * 4)
#define CLIP_T   256
#define PREF_ROWS 128

// ---- device scratch (no allocations allowed; .bss zero-initialized) ----
__device__ float4 g_box[MAXN];        // bx, by, rad, area
__device__ float4 g_crn[MAXN * 2];    // (x0,y0,x1,y1), (x2,y2,x3,y3)
__device__ unsigned long long g_mask[MAXN * WWORDS];   // self-cleaned
__device__ unsigned long long g_rowflag[WWORDS];       // self-cleaned
__device__ unsigned int g_pairs[MAXPAIRS];
__device__ int g_npairs;
__device__ unsigned int g_done;                        // self-cleaned

// ---------------------------------------------------------------------------
// Kernel 1: per-box data (corners, circle, area).
// ---------------------------------------------------------------------------
__global__ void prep_kernel(const float* __restrict__ boxes, int N)
{
    int tid = blockIdx.x * blockDim.x + threadIdx.x;
    if (tid == 0) g_npairs = 0;
    if (tid < N) {
        float xc = boxes[tid * 5 + 0];
        float yc = boxes[tid * 5 + 1];
        float w  = boxes[tid * 5 + 2];
        float h  = boxes[tid * 5 + 3];
        float t  = boxes[tid * 5 + 4];
        float th = t * (float)(M_PI / 180.0);
        float c = cosf(th), s = sinf(th);
        const float lx[4] = { 0.5f, -0.5f, -0.5f,  0.5f };
        const float ly[4] = { 0.5f,  0.5f, -0.5f, -0.5f };
        float cx[4], cy[4];
#pragma unroll
        for (int k = 0; k < 4; ++k) {
            cx[k] = xc + lx[k] * w * c - ly[k] * h * s;
            cy[k] = yc + lx[k] * w * s + ly[k] * h * c;
        }
        g_crn[tid * 2 + 0] = make_float4(cx[0], cy[0], cx[1], cy[1]);
        g_crn[tid * 2 + 1] = make_float4(cx[2], cy[2], cx[3], cy[3]);
        g_box[tid] = make_float4(xc, yc, 0.5f * sqrtf(w * w + h * h), w * h);
    }
}

// ---------------------------------------------------------------------------
// Kernel 2: pre-filter over folded triangle -> worklist. 4 jj per thread.
// Filters: bounding-circle contact AND exact area-ratio IoU upper bound
// (iou <= min_area / max(ai+aj-min_area, EPS); skip if <= 0.7).
// blockIdx.y = i0 in [0, M/2); x*4 covers jj in [0, M).
// ---------------------------------------------------------------------------
__global__ void pairgen_kernel(int N, int M)   // M = N rounded up to even
{
    int i0 = blockIdx.y;
    int jb = (blockIdx.x * blockDim.x + threadIdx.x) * 4;
    int lane = threadIdx.x & 31;

    unsigned cand[4];
    int cnt = 0;

    // uniform i-side data for the two fold branches
    float4 biA = g_box[i0];                     // for jj > i0
    int iB = M - 1 - i0;                        // for jj < i0
    float4 biB = (iB < N) ? g_box[iB] : make_float4(0.f, 0.f, -1e9f, 0.f);

#pragma unroll
    for (int u = 0; u < 4; ++u) {
        int jj = jb + u;
        if (jj >= M) break;
        int i, j;
        float4 bi;
        if (jj > i0)      { i = i0; j = jj; bi = biA; }
        else if (jj < i0) { i = iB; j = M - 1 - jj; bi = biB; }
        else continue;
        if (i >= N || j >= N) continue;
        float4 bj = g_box[j];
        float dx = bi.x - bj.x;
        float dy = bi.y - bj.y;
        float rr = bi.z + bj.z;
        if (dx * dx + dy * dy <= rr * rr) {
            float mn = fminf(bi.w, bj.w);
            float bound = mn / fmaxf(bi.w + bj.w - mn, EPSF);
            if (bound > NMS_THR)
                cand[cnt++] = ((unsigned)i << 11) | (unsigned)j;
        }
    }

    // warp-aggregated append of 0..4 survivors per lane
    unsigned any = __ballot_sync(0xffffffffu, cnt > 0);
    if (any) {
        int incl = cnt;
#pragma unroll
        for (int off = 1; off < 32; off <<= 1) {
            int v = __shfl_up_sync(0xffffffffu, incl, off);
            if (lane >= off) incl += v;
        }
        int total = __shfl_sync(0xffffffffu, incl, 31);
        int base = 0;
        if (lane == 31) base = atomicAdd(&g_npairs, total);
        base = __shfl_sync(0xffffffffu, base, 31);
        int pos = base + incl - cnt;
        for (int u = 0; u < cnt; ++u) g_pairs[pos + u] = cand[u];
    }
}

// ---------------------------------------------------------------------------
// nms body (runs in the LAST clip block, 256 threads): greedy suppression
// over flagged rows only, then block-wide compaction. Self-cleans state.
// ---------------------------------------------------------------------------
__device__ void nms_body(float* __restrict__ out, int N, int out_size)
{
    __shared__ unsigned long long s_flag[WWORDS];
    __shared__ unsigned long long s_rem[WWORDS];
    __shared__ unsigned long long s_kept[WWORDS];
    __shared__ int s_wexcl[WWORDS + 1];
    __shared__ short s_rowlist[MAXN];
    __shared__ int s_nrows;
    __shared__ unsigned long long s_rowdata[PREF_ROWS][WWORDS];   // 32 KB

    int tid = threadIdx.x;
    int lane = tid & 31, wid = tid >> 5;

    if (tid < WWORDS) { s_flag[tid] = g_rowflag[tid]; s_rem[tid] = 0ULL; }
    __syncthreads();

    if (wid == 0) {
        int pc = __popcll(s_flag[lane]);
        int incl = pc;
#pragma unroll
        for (int off = 1; off < 32; off <<= 1) {
            int v = __shfl_up_sync(0xffffffffu, incl, off);
            if (lane >= off) incl += v;
        }
        s_wexcl[lane] = incl - pc;
        if (lane == 31) s_nrows = incl;
    }
    __syncthreads();
    int nrows = s_nrows;

    for (int p = tid; p < MAXN; p += CLIP_T) {
        int w = p >> 6, b = p & 63;
        unsigned long long f = s_flag[w];
        if ((f >> b) & 1ULL) {
            int pos = s_wexcl[w] + __popcll(f & ((1ULL << b) - 1ULL));
            s_rowlist[pos] = (short)p;
        }
    }
    __syncthreads();

    int npf = nrows < PREF_ROWS ? nrows : PREF_ROWS;
    for (int idx = tid; idx < npf * WWORDS; idx += CLIP_T) {
        int r = idx >> 5, w = idx & 31;
        s_rowdata[r][w] = g_mask[(int)s_rowlist[r] * WWORDS + w];
    }
    __syncthreads();

    if (wid == 0) {
        for (int r = 0; r < nrows; ++r) {
            int i = (int)s_rowlist[r];
            if (!((s_rem[i >> 6] >> (i & 63)) & 1ULL)) {
                unsigned long long row = (r < PREF_ROWS)
                    ? s_rowdata[r][lane]
                    : g_mask[i * WWORDS + lane];
                s_rem[lane] |= row;
            }
            __syncwarp();
        }
        unsigned long long kept = ~s_rem[lane];
        int base = lane * 64;
        int nb = N - base;
        if (nb <= 0) kept = 0ULL;
        else if (nb < 64) kept &= (~0ULL) >> (64 - nb);
        s_kept[lane] = kept;
        int pc = __popcll(kept);
        int incl = pc;
#pragma unroll
        for (int off = 1; off < 32; off <<= 1) {
            int v = __shfl_up_sync(0xffffffffu, incl, off);
            if (lane >= off) incl += v;
        }
        s_wexcl[lane] = incl - pc;
        if (lane == 31) s_wexcl[32] = incl;
    }
    __syncthreads();

    // self-clean dirty rows + rowflag + done counter
    for (int idx = tid; idx < nrows * WWORDS; idx += CLIP_T)
        g_mask[(int)s_rowlist[idx >> 5] * WWORDS + (idx & 31)] = 0ULL;
    if (tid < WWORDS) g_rowflag[tid] = 0ULL;
    if (tid == 0) g_done = 0;

    int total = s_wexcl[32];
    for (int p = tid; p < MAXN; p += CLIP_T) {
        int w = p >> 6, b = p & 63;
        unsigned long long k = s_kept[w];
        if ((k >> b) & 1ULL) {
            int pos = s_wexcl[w] + __popcll(k & ((1ULL << b) - 1ULL));
            if (pos < out_size) out[pos] = (float)p;
        }
    }
    for (int p = total + tid; p < out_size; p += CLIP_T) out[p] = -1.0f;
}

// ---------------------------------------------------------------------------
// Kernel 3: dense polygon-clip IoU over the worklist -> suppression bitmask
// (math byte-identical to the reference path), then the LAST block to finish
// runs the greedy-NMS + compaction body.
// ---------------------------------------------------------------------------
__global__ void __launch_bounds__(CLIP_T)
clipnms_kernel(float* __restrict__ out, int N, int out_size)
{
    int np = g_npairs;
    int stride = gridDim.x * blockDim.x;
    for (int idx = blockIdx.x * blockDim.x + threadIdx.x; idx < np; idx += stride) {
        unsigned pr = g_pairs[idx];
        int i = (int)(pr >> 11);
        int j = (int)(pr & 0x7FFu);

        float p1x[4], p1y[4], q1x[4], q1y[4];
        {
            float4 a0 = g_crn[i * 2 + 0], a1 = g_crn[i * 2 + 1];
            float4 b0 = g_crn[j * 2 + 0], b1 = g_crn[j * 2 + 1];
            p1x[0] = a0.x; p1y[0] = a0.y; p1x[1] = a0.z; p1y[1] = a0.w;
            p1x[2] = a1.x; p1y[2] = a1.y; p1x[3] = a1.z; p1y[3] = a1.w;
            q1x[0] = b0.x; q1y[0] = b0.y; q1x[1] = b0.z; q1y[1] = b0.w;
            q1x[2] = b1.x; q1y[2] = b1.y; q1x[3] = b1.z; q1y[3] = b1.w;
        }
        float d1x[4], d1y[4], d2x[4], d2y[4];
#pragma unroll
        for (int k = 0; k < 4; ++k) {
            int kn = (k + 1) & 3;
            d1x[k] = p1x[kn] - p1x[k];  d1y[k] = p1y[kn] - p1y[k];
            d2x[k] = q1x[kn] - q1x[k];  d2y[k] = q1y[kn] - q1y[k];
        }

        float vx[24], vy[24], va[24];
        int nv = 0;

#pragma unroll
        for (int a = 0; a < 4; ++a) {
#pragma unroll
            for (int b = 0; b < 4; ++b) {
                float denom = d1x[a] * d2y[b] - d1y[a] * d2x[b];
                if (fabsf(denom) > EPSF) {
                    float rpx = q1x[b] - p1x[a];
                    float rpy = q1y[b] - p1y[a];
                    float t = (rpx * d2y[b] - rpy * d2x[b]) / denom;
                    float u = (rpx * d1y[a] - rpy * d1x[a]) / denom;
                    if (t >= 0.0f && t <= 1.0f && u >= 0.0f && u <= 1.0f) {
                        vx[nv] = p1x[a] + t * d1x[a];
                        vy[nv] = p1y[a] + t * d1y[a];
                        ++nv;
                    }
                }
            }
        }

#pragma unroll
        for (int a = 0; a < 4; ++a) {
            bool ge = true, le = true;
#pragma unroll
            for (int b = 0; b < 4; ++b) {
                float cvx = p1x[a] - q1x[b];
                float cvy = p1y[a] - q1y[b];
                float cr = d2x[b] * cvy - d2y[b] * cvx;
                ge = ge && (cr >= -EPSF);
                le = le && (cr <=  EPSF);
            }
            if (ge || le) { vx[nv] = p1x[a]; vy[nv] = p1y[a]; ++nv; }
        }
#pragma unroll
        for (int b = 0; b < 4; ++b) {
            bool ge = true, le = true;
#pragma unroll
            for (int a = 0; a < 4; ++a) {
                float cvx = q1x[b] - p1x[a];
                float cvy = q1y[b] - p1y[a];
                float cr = d1x[a] * cvy - d1y[a] * cvx;
                ge = ge && (cr >= -EPSF);
                le = le && (cr <=  EPSF);
            }
            if (ge || le) { vx[nv] = q1x[b]; vy[nv] = q1y[b]; ++nv; }
        }

        float inter = 0.0f;
        if (nv >= 3) {
            float sx = 0.0f, sy = 0.0f;
            for (int k = 0; k < nv; ++k) { sx += vx[k]; sy += vy[k]; }
            float cx = sx / (float)nv;
            float cy = sy / (float)nv;
            for (int k = 0; k < nv; ++k)
                va[k] = atan2f(vy[k] - cy, vx[k] - cx);

            for (int k = 1; k < nv; ++k) {
                float a = va[k], x = vx[k], y = vy[k];
                int m = k - 1;
                while (m >= 0 && va[m] > a) {
                    va[m + 1] = va[m]; vx[m + 1] = vx[m]; vy[m + 1] = vy[m];
                    --m;
                }
                va[m + 1] = a; vx[m + 1] = x; vy[m + 1] = y;
            }

            float s = 0.0f;
            for (int k = 0; k < nv; ++k) {
                int kn = (k + 1 == nv) ? 0 : k + 1;
                s += (vx[k] - cx) * (vy[kn] - cy) - (vy[k] - cy) * (vx[kn] - cx);
            }
            inter = 0.5f * fabsf(s);
        }

        float ai = g_box[i].w, aj = g_box[j].w;
        float uni = ai + aj - inter;
        float iou = inter / fmaxf(uni, EPSF);
        if (iou > NMS_THR) {
            atomicOr(&g_mask[i * WWORDS + (j >> 6)], 1ULL << (j & 63));
            atomicOr(&g_rowflag[i >> 6], 1ULL << (i & 63));
        }
    }

    // last-block-done: the final block to arrive runs the NMS + compaction
    __syncthreads();
    __shared__ int s_last;
    if (threadIdx.x == 0) {
        __threadfence();
        unsigned v = atomicAdd(&g_done, 1u);
        s_last = (v == gridDim.x - 1u) ? 1 : 0;
    }
    __syncthreads();
    if (s_last) {
        __threadfence();   // acquire: all other blocks' mask writes visible
        nms_body(out, N, out_size);
    }
}

// ---------------------------------------------------------------------------
extern "C" void kernel_launch(void* const* d_in, const int* in_sizes, int n_in,
                              void* d_out, int out_size)
{
    const float* boxes = (const float*)d_in[0];
    int N = in_sizes[0] / 5;
    if (N > MAXN) N = MAXN;
    float* out = (float*)d_out;

    {
        int threads = 256;
        int blocks = (N + threads - 1) / threads;
        prep_kernel<<<blocks, threads>>>(boxes, N);
    }
    {
        int M = (N + 1) & ~1;                 // even
        int jthreads = (M + 3) / 4;           // 4 jj per thread
        dim3 grid((jthreads + 255) / 256, M >> 1);
        pairgen_kernel<<<grid, 256>>>(N, M);
    }
    clipnms_kernel<<<CLIP_BLOCKS, CLIP_T>>>(out, N, out_size);
}